// round 3
// baseline (speedup 1.0000x reference)
#include <cuda_runtime.h>
#include <cstdint>

// ---------------------------------------------------------------------------
// GCN 2-layer + linear head.
//   h1 = relu(gcnconv(x, W1) + b1)       x:[N,32] W1:[32,64]
//   h2 = relu(gcnconv(h1, W2) + b2)      W2:[64,64]
//   q  = h2 @ Wl + bl                    Wl:[64,2]
// gcnconv: h = x@W;  agg[d] += h[s] * dinv[s]*dinv[d]  (+ self loop h[i]*dinv[i]^2)
// ---------------------------------------------------------------------------

#define N_NODES 50000
#define HID 64

// scratch (__device__ globals: no allocation allowed)
__device__ float g_deg[N_NODES];
__device__ float g_dinv[N_NODES];
__device__ float g_h[(size_t)N_NODES * HID];    // post-GEMM features
__device__ float g_agg[(size_t)N_NODES * HID];  // aggregation target
__device__ int   g_is64;                        // edge_index dtype flag

// ---------------- dtype detection ----------------
// If edge_index is int64 (values < 50000), every odd 32-bit word of the first
// E int64s is zero. If it is int32, odd words are edge indices (random,
// ~never all zero over 2048 samples). Reading the first 2E words is safe in
// both interpretations.
__global__ void k_detect(const unsigned int* __restrict__ w, int nwords) {
    __shared__ int any_nz;
    if (threadIdx.x == 0) any_nz = 0;
    __syncthreads();
    for (int i = threadIdx.x * 2 + 1; i < nwords; i += blockDim.x * 2) {
        if (w[i] != 0u) { any_nz = 1; break; }
    }
    __syncthreads();
    if (threadIdx.x == 0) g_is64 = any_nz ? 0 : 1;
}

__device__ __forceinline__ int edge_at(const void* __restrict__ ei, int i) {
    if (g_is64) return (int)((const long long*)ei)[i];
    return ((const int*)ei)[i];
}

// ---------------- degree / norm ----------------
__global__ void k_deg_init(int n) {
    int i = blockIdx.x * blockDim.x + threadIdx.x;
    if (i < n) g_deg[i] = 1.0f;  // self loop
}

__global__ void k_deg_count(const void* __restrict__ ei, int E) {
    int e = blockIdx.x * blockDim.x + threadIdx.x;
    if (e < E) {
        int d = edge_at(ei, E + e);  // dst row
        atomicAdd(&g_deg[d], 1.0f);
    }
}

__global__ void k_dinv(int n) {
    int i = blockIdx.x * blockDim.x + threadIdx.x;
    if (i < n) g_dinv[i] = rsqrtf(g_deg[i]);
}

// ---------------- small GEMM: [n,K] @ [K,64] -> g_h[n,64] ----------------
// One thread per node, W staged in smem. SRC_AGG: read g_agg (device symbol)
// instead of the `in` pointer, with fused (v + b) relu.
template <int K, bool SRC_AGG>
__global__ void k_gemm64(const float* __restrict__ in, const float* __restrict__ W,
                         const float* __restrict__ bin, int n) {
    __shared__ float Ws[K * 64];
    __shared__ float bs[K];
    for (int i = threadIdx.x; i < K * 64; i += blockDim.x) Ws[i] = W[i];
    if (SRC_AGG)
        for (int i = threadIdx.x; i < K; i += blockDim.x) bs[i] = bin[i];
    __syncthreads();

    int node = blockIdx.x * blockDim.x + threadIdx.x;
    if (node >= n) return;

    float acc[64];
#pragma unroll
    for (int j = 0; j < 64; j++) acc[j] = 0.0f;

    const float* row = SRC_AGG ? (g_agg + (size_t)node * K) : (in + (size_t)node * K);
#pragma unroll 4
    for (int k = 0; k < K; k++) {
        float v = row[k];
        if (SRC_AGG) v = fmaxf(v + bs[k], 0.0f);
#pragma unroll
        for (int j = 0; j < 64; j++) acc[j] = fmaf(v, Ws[k * 64 + j], acc[j]);
    }
    float* o = g_h + (size_t)node * 64;
#pragma unroll
    for (int j = 0; j < 64; j++) o[j] = acc[j];
}

// ---------------- self-loop init: agg[n] = h[n] * dinv[n]^2 ----------------
__global__ void k_selfloop(int n) {
    int t = blockIdx.x * blockDim.x + threadIdx.x;  // over n*64
    if (t >= n * HID) return;
    int node = t >> 6;
    float dv = g_dinv[node];
    g_agg[t] = g_h[t] * dv * dv;
}

// ---------------- edge scatter: agg[dst] += h[src] * dinv[s]*dinv[d] -------
// 16 threads per edge, float4 per thread, vector RED (atomicAdd float4).
__global__ void k_scatter(const void* __restrict__ ei, int E) {
    int t = blockIdx.x * blockDim.x + threadIdx.x;
    int e = t >> 4;
    if (e >= E) return;
    int q = t & 15;
    int s = edge_at(ei, e);
    int d = edge_at(ei, E + e);
    float norm = g_dinv[s] * g_dinv[d];
    const float4 v = *reinterpret_cast<const float4*>(g_h + (size_t)s * HID + q * 4);
    float4* o = reinterpret_cast<float4*>(g_agg + (size_t)d * HID + q * 4);
    atomicAdd(o, make_float4(v.x * norm, v.y * norm, v.z * norm, v.w * norm));
}

// ---------------- final head: q = relu(agg + b2) @ Wl + bl ----------------
__global__ void k_head(const float* __restrict__ b2, const float* __restrict__ Wl,
                       const float* __restrict__ bl, float* __restrict__ out, int n) {
    __shared__ float Ws[64 * 2];
    __shared__ float bs[64];
    for (int i = threadIdx.x; i < 128; i += blockDim.x) Ws[i] = Wl[i];
    for (int i = threadIdx.x; i < 64; i += blockDim.x) bs[i] = b2[i];
    __syncthreads();

    int node = blockIdx.x * blockDim.x + threadIdx.x;
    if (node >= n) return;
    const float* row = g_agg + (size_t)node * 64;
    float a0 = 0.0f, a1 = 0.0f;
#pragma unroll
    for (int k = 0; k < 64; k++) {
        float v = fmaxf(row[k] + bs[k], 0.0f);
        a0 = fmaf(v, Ws[k * 2 + 0], a0);
        a1 = fmaf(v, Ws[k * 2 + 1], a1);
    }
    out[(size_t)node * 2 + 0] = a0 + bl[0];
    out[(size_t)node * 2 + 1] = a1 + bl[1];
}

// ---------------------------------------------------------------------------
extern "C" void kernel_launch(void* const* d_in, const int* in_sizes, int n_in,
                              void* d_out, int out_size) {
    const float* x   = (const float*)d_in[0];   // [N,32]
    const void*  ei  = d_in[1];                 // [2,E] int32 or int64
    const float* W1  = (const float*)d_in[2];   // [32,64]
    const float* b1  = (const float*)d_in[3];   // [64]
    const float* W2  = (const float*)d_in[4];   // [64,64]
    const float* b2  = (const float*)d_in[5];   // [64]
    const float* Wl  = (const float*)d_in[6];   // [64,2]
    const float* bl  = (const float*)d_in[7];   // [2]
    float* out       = (float*)d_out;           // [N,2]

    const int N = in_sizes[0] / 32;
    const int E = in_sizes[1] / 2;

    const int T = 256;

    // dtype detection (safe to read first 2E 32-bit words either way)
    int nwords = 2 * E < 4096 ? 2 * E : 4096;
    k_detect<<<1, 256>>>((const unsigned int*)ei, nwords);

    // degree + norm
    k_deg_init<<<(N + T - 1) / T, T>>>(N);
    k_deg_count<<<(E + T - 1) / T, T>>>(ei, E);
    k_dinv<<<(N + T - 1) / T, T>>>(N);

    // ---- layer 1 ----
    k_gemm64<32, false><<<(N + 127) / 128, 128>>>(x, W1, nullptr, N);
    k_selfloop<<<(N * HID + T - 1) / T, T>>>(N);
    {
        long long tot = (long long)E * 16;
        k_scatter<<<(int)((tot + T - 1) / T), T>>>(ei, E);
    }

    // ---- layer 2 (fused relu(agg+b1) into GEMM input; reads g_agg directly) ----
    k_gemm64<64, true><<<(N + 127) / 128, 128>>>(nullptr, W2, b1, N);
    k_selfloop<<<(N * HID + T - 1) / T, T>>>(N);
    {
        long long tot = (long long)E * 16;
        k_scatter<<<(int)((tot + T - 1) / T), T>>>(ei, E);
    }

    // ---- head ----
    k_head<<<(N + T - 1) / T, T>>>(b2, Wl, bl, out, N);
}

// round 4
// speedup vs baseline: 1.9419x; 1.9419x over previous
#include <cuda_runtime.h>
#include <cstdint>

// ---------------------------------------------------------------------------
// GCN 2-layer + linear head, CSR-gather formulation (no float atomics).
//   h = x@W;  agg[d] = dinv[d] * ( sum_{s->d} dinv[s]*h[s] + dinv[d]*h[d] )
// ---------------------------------------------------------------------------

#define N_NODES 50000
#define MAX_E   1000000
#define HID 64

// scratch (__device__ globals: no allocation allowed)
__device__ int   g_degi[N_NODES];      // in-degree (edges only)
__device__ int   g_off[N_NODES];       // CSR offsets (exclusive scan)
__device__ int   g_cur[N_NODES];       // fill cursors
__device__ int   g_bsum[256];          // scan block sums
__device__ int   g_bpre[256];          // scan block prefixes
__device__ int   g_csr_src[MAX_E];     // edge sources bucketed by dst
__device__ float g_dinv[N_NODES];
__device__ float g_h[(size_t)N_NODES * HID];    // post-GEMM features
__device__ float g_agg[(size_t)N_NODES * HID];  // aggregation result
__device__ int   g_is64;               // edge_index dtype flag

// ---------------- dtype detection ----------------
__global__ void k_detect(const unsigned int* __restrict__ w, int nwords) {
    __shared__ int any_nz;
    if (threadIdx.x == 0) any_nz = 0;
    __syncthreads();
    for (int i = threadIdx.x * 2 + 1; i < nwords; i += blockDim.x * 2) {
        if (w[i] != 0u) { any_nz = 1; break; }
    }
    __syncthreads();
    if (threadIdx.x == 0) g_is64 = any_nz ? 0 : 1;
}

__device__ __forceinline__ int edge_at(const void* __restrict__ ei, int i) {
    if (g_is64) return (int)((const long long*)ei)[i];
    return ((const int*)ei)[i];
}

// ---------------- degree count ----------------
__global__ void k_zero(int n) {
    int i = blockIdx.x * blockDim.x + threadIdx.x;
    if (i < n) g_degi[i] = 0;
}

__global__ void k_count(const void* __restrict__ ei, int E) {
    int e = blockIdx.x * blockDim.x + threadIdx.x;
    if (e < E) atomicAdd(&g_degi[edge_at(ei, E + e)], 1);
}

// ---------------- 3-stage exclusive scan over g_degi -> g_off ----------------
__global__ void k_scan_block(int n) {
    __shared__ int s[256];
    int i = blockIdx.x * 256 + threadIdx.x;
    int v = (i < n) ? g_degi[i] : 0;
    s[threadIdx.x] = v;
    __syncthreads();
#pragma unroll
    for (int off = 1; off < 256; off <<= 1) {
        int t = (threadIdx.x >= off) ? s[threadIdx.x - off] : 0;
        __syncthreads();
        s[threadIdx.x] += t;
        __syncthreads();
    }
    if (i < n) g_off[i] = s[threadIdx.x] - v;  // exclusive
    if (threadIdx.x == 255) g_bsum[blockIdx.x] = s[255];
}

__global__ void k_scan_top(int nb) {
    __shared__ int s[256];
    int v = (threadIdx.x < nb) ? g_bsum[threadIdx.x] : 0;
    s[threadIdx.x] = v;
    __syncthreads();
#pragma unroll
    for (int off = 1; off < 256; off <<= 1) {
        int t = (threadIdx.x >= off) ? s[threadIdx.x - off] : 0;
        __syncthreads();
        s[threadIdx.x] += t;
        __syncthreads();
    }
    g_bpre[threadIdx.x] = s[threadIdx.x] - v;  // exclusive
}

// finalize offsets, init cursors, compute dinv (deg + self loop)
__global__ void k_finalize(int n) {
    int i = blockIdx.x * blockDim.x + threadIdx.x;
    if (i >= n) return;
    int off = g_off[i] + g_bpre[i >> 8];
    g_off[i] = off;
    g_cur[i] = off;
    g_dinv[i] = rsqrtf((float)(g_degi[i] + 1));
}

// ---------------- CSR fill ----------------
__global__ void k_csr_fill(const void* __restrict__ ei, int E) {
    int e = blockIdx.x * blockDim.x + threadIdx.x;
    if (e >= E) return;
    int s = edge_at(ei, e);
    int d = edge_at(ei, E + e);
    int slot = atomicAdd(&g_cur[d], 1);
    g_csr_src[slot] = s;
}

// ---------------- small GEMM: [n,K] @ [K,64] -> g_h[n,64] ----------------
template <int K, bool SRC_AGG>
__global__ void k_gemm64(const float* __restrict__ in, const float* __restrict__ W,
                         const float* __restrict__ bin, int n) {
    __shared__ float Ws[K * 64];
    __shared__ float bs[K];
    for (int i = threadIdx.x; i < K * 64; i += blockDim.x) Ws[i] = W[i];
    if (SRC_AGG)
        for (int i = threadIdx.x; i < K; i += blockDim.x) bs[i] = bin[i];
    __syncthreads();

    int node = blockIdx.x * blockDim.x + threadIdx.x;
    if (node >= n) return;

    float acc[64];
#pragma unroll
    for (int j = 0; j < 64; j++) acc[j] = 0.0f;

    const float* row = SRC_AGG ? (g_agg + (size_t)node * K) : (in + (size_t)node * K);
#pragma unroll 4
    for (int k = 0; k < K; k++) {
        float v = row[k];
        if (SRC_AGG) v = fmaxf(v + bs[k], 0.0f);
#pragma unroll
        for (int j = 0; j < 64; j++) acc[j] = fmaf(v, Ws[k * 64 + j], acc[j]);
    }
    float* o = g_h + (size_t)node * 64;
#pragma unroll
    for (int j = 0; j < 64; j++) o[j] = acc[j];
}

// ---------------- gather: one warp per node, 2 floats per lane ----------------
// agg[d] = dinv[d] * ( sum_e dinv[src]*h[src] + dinv[d]*h[d] )
__global__ void k_gather(int n) {
    int warp = (blockIdx.x * blockDim.x + threadIdx.x) >> 5;
    if (warp >= n) return;
    int lane = threadIdx.x & 31;

    const int beg = g_off[warp];
    const int cnt = g_degi[warp];
    const float dv = g_dinv[warp];
    const float2* hp = reinterpret_cast<const float2*>(g_h);

    // self loop contribution: dinv[d]*h[d]
    float2 self = hp[(size_t)warp * 32 + lane];
    float ax = self.x * dv, ay = self.y * dv;
    float bx = 0.f, by = 0.f;  // second accumulator for ILP

    int e = 0;
    // unrolled by 2: independent index loads -> overlapped latency
    for (; e + 2 <= cnt; e += 2) {
        int s0 = g_csr_src[beg + e];
        int s1 = g_csr_src[beg + e + 1];
        float w0 = g_dinv[s0];
        float w1 = g_dinv[s1];
        float2 v0 = hp[(size_t)s0 * 32 + lane];
        float2 v1 = hp[(size_t)s1 * 32 + lane];
        ax = fmaf(v0.x, w0, ax); ay = fmaf(v0.y, w0, ay);
        bx = fmaf(v1.x, w1, bx); by = fmaf(v1.y, w1, by);
    }
    if (e < cnt) {
        int s0 = g_csr_src[beg + e];
        float w0 = g_dinv[s0];
        float2 v0 = hp[(size_t)s0 * 32 + lane];
        ax = fmaf(v0.x, w0, ax); ay = fmaf(v0.y, w0, ay);
    }

    float2 r;
    r.x = (ax + bx) * dv;
    r.y = (ay + by) * dv;
    reinterpret_cast<float2*>(g_agg)[(size_t)warp * 32 + lane] = r;
}

// ---------------- final head: q = relu(agg + b2) @ Wl + bl ----------------
__global__ void k_head(const float* __restrict__ b2, const float* __restrict__ Wl,
                       const float* __restrict__ bl, float* __restrict__ out, int n) {
    __shared__ float Ws[64 * 2];
    __shared__ float bs[64];
    for (int i = threadIdx.x; i < 128; i += blockDim.x) Ws[i] = Wl[i];
    for (int i = threadIdx.x; i < 64; i += blockDim.x) bs[i] = b2[i];
    __syncthreads();

    int node = blockIdx.x * blockDim.x + threadIdx.x;
    if (node >= n) return;
    const float* row = g_agg + (size_t)node * 64;
    float a0 = 0.0f, a1 = 0.0f;
#pragma unroll
    for (int k = 0; k < 64; k++) {
        float v = fmaxf(row[k] + bs[k], 0.0f);
        a0 = fmaf(v, Ws[k * 2 + 0], a0);
        a1 = fmaf(v, Ws[k * 2 + 1], a1);
    }
    out[(size_t)node * 2 + 0] = a0 + bl[0];
    out[(size_t)node * 2 + 1] = a1 + bl[1];
}

// ---------------------------------------------------------------------------
extern "C" void kernel_launch(void* const* d_in, const int* in_sizes, int n_in,
                              void* d_out, int out_size) {
    const float* x   = (const float*)d_in[0];   // [N,32]
    const void*  ei  = d_in[1];                 // [2,E] int32 or int64
    const float* W1  = (const float*)d_in[2];   // [32,64]
    const float* b1  = (const float*)d_in[3];   // [64]
    const float* W2  = (const float*)d_in[4];   // [64,64]
    const float* b2  = (const float*)d_in[5];   // [64]
    const float* Wl  = (const float*)d_in[6];   // [64,2]
    const float* bl  = (const float*)d_in[7];   // [2]
    float* out       = (float*)d_out;           // [N,2]

    const int N = in_sizes[0] / 32;
    const int E = in_sizes[1] / 2;
    const int T = 256;
    const int NB = (N + 255) / 256;  // scan blocks (<= 256 for N <= 65536)

    // dtype detection
    int nwords = 2 * E < 4096 ? 2 * E : 4096;
    k_detect<<<1, 256>>>((const unsigned int*)ei, nwords);

    // CSR build (shared by both layers)
    k_zero<<<(N + T - 1) / T, T>>>(N);
    k_count<<<(E + T - 1) / T, T>>>(ei, E);
    k_scan_block<<<NB, 256>>>(N);
    k_scan_top<<<1, 256>>>(NB);
    k_finalize<<<(N + T - 1) / T, T>>>(N);
    k_csr_fill<<<(E + T - 1) / T, T>>>(ei, E);

    const int GW = (N * 32 + T - 1) / T;  // gather grid (warp per node)

    // ---- layer 1 ----
    k_gemm64<32, false><<<(N + 127) / 128, 128>>>(x, W1, nullptr, N);
    k_gather<<<GW, T>>>(N);

    // ---- layer 2 (fused relu(agg+b1) into GEMM input) ----
    k_gemm64<64, true><<<(N + 127) / 128, 128>>>(nullptr, W2, b1, N);
    k_gather<<<GW, T>>>(N);

    // ---- head ----
    k_head<<<(N + T - 1) / T, T>>>(b2, Wl, bl, out, N);
}

// round 5
// speedup vs baseline: 2.4621x; 1.2679x over previous
#include <cuda_runtime.h>
#include <cstdint>

// ---------------------------------------------------------------------------
// GCN 2-layer + linear head, CSR-gather formulation (no float atomics).
//   h = x@W;  agg[d] = dinv[d] * ( sum_{s->d} dinv[s]*h[s] + dinv[d]*h[d] )
// CSR entries carry (src, dinv[src]) packed in 8B to cut a dependent load.
// ---------------------------------------------------------------------------

#define N_NODES 50000
#define MAX_E   1000000
#define HID 64

struct alignas(8) Ent { int s; float w; };

// scratch (__device__ globals: no allocation allowed)
__device__ int   g_degi[N_NODES];      // in-degree (edges only)
__device__ int   g_off[N_NODES];       // CSR offsets (exclusive scan)
__device__ int   g_cur[N_NODES];       // fill cursors
__device__ int   g_bsum[256];          // scan block sums
__device__ int   g_bpre[256];          // scan block prefixes
__device__ Ent   g_csr[MAX_E];         // (src, dinv[src]) bucketed by dst
__device__ float g_dinv[N_NODES];
__device__ float g_h[(size_t)N_NODES * HID];    // post-GEMM features
__device__ float g_agg[(size_t)N_NODES * HID];  // aggregation result
__device__ int   g_is64;               // edge_index dtype flag

// ---------------- init: zero degrees + dtype detection (block 0) -----------
__global__ void k_init(const unsigned int* __restrict__ w, int nwords, int n) {
    int i = blockIdx.x * blockDim.x + threadIdx.x;
    if (i < n) g_degi[i] = 0;
    if (blockIdx.x == 0) {
        __shared__ int any_nz;
        if (threadIdx.x == 0) any_nz = 0;
        __syncthreads();
        for (int j = threadIdx.x * 2 + 1; j < nwords; j += blockDim.x * 2) {
            if (w[j] != 0u) { any_nz = 1; break; }
        }
        __syncthreads();
        if (threadIdx.x == 0) g_is64 = any_nz ? 0 : 1;
    }
}

__device__ __forceinline__ int edge_at(const void* __restrict__ ei, int i) {
    if (g_is64) return (int)((const long long*)ei)[i];
    return ((const int*)ei)[i];
}

__global__ void k_count(const void* __restrict__ ei, int E) {
    int e = blockIdx.x * blockDim.x + threadIdx.x;
    if (e < E) atomicAdd(&g_degi[edge_at(ei, E + e)], 1);
}

// ---------------- 3-stage exclusive scan over g_degi -> g_off ----------------
__global__ void k_scan_block(int n) {
    __shared__ int s[256];
    int i = blockIdx.x * 256 + threadIdx.x;
    int v = (i < n) ? g_degi[i] : 0;
    s[threadIdx.x] = v;
    __syncthreads();
#pragma unroll
    for (int off = 1; off < 256; off <<= 1) {
        int t = (threadIdx.x >= off) ? s[threadIdx.x - off] : 0;
        __syncthreads();
        s[threadIdx.x] += t;
        __syncthreads();
    }
    if (i < n) g_off[i] = s[threadIdx.x] - v;  // exclusive
    if (threadIdx.x == 255) g_bsum[blockIdx.x] = s[255];
}

__global__ void k_scan_top(int nb) {
    __shared__ int s[256];
    int v = (threadIdx.x < nb) ? g_bsum[threadIdx.x] : 0;
    s[threadIdx.x] = v;
    __syncthreads();
#pragma unroll
    for (int off = 1; off < 256; off <<= 1) {
        int t = (threadIdx.x >= off) ? s[threadIdx.x - off] : 0;
        __syncthreads();
        s[threadIdx.x] += t;
        __syncthreads();
    }
    g_bpre[threadIdx.x] = s[threadIdx.x] - v;  // exclusive
}

// finalize offsets, init cursors, compute dinv (deg + self loop)
__global__ void k_finalize(int n) {
    int i = blockIdx.x * blockDim.x + threadIdx.x;
    if (i >= n) return;
    int off = g_off[i] + g_bpre[i >> 8];
    g_off[i] = off;
    g_cur[i] = off;
    g_dinv[i] = rsqrtf((float)(g_degi[i] + 1));
}

// ---------------- CSR fill: store (src, dinv[src]) ----------------
__global__ void k_csr_fill(const void* __restrict__ ei, int E) {
    int e = blockIdx.x * blockDim.x + threadIdx.x;
    if (e >= E) return;
    int s = edge_at(ei, e);
    int d = edge_at(ei, E + e);
    int slot = atomicAdd(&g_cur[d], 1);
    Ent en; en.s = s; en.w = g_dinv[s];
    g_csr[slot] = en;
}

// ---------------- small GEMM: [n,K] @ [K,64] -> g_h[n,64] ----------------
// One thread per node, W in smem, float4 row loads, optional fused bias+relu.
template <int K, bool SRC_AGG>
__global__ void k_gemm64(const float* __restrict__ in, const float* __restrict__ W,
                         const float* __restrict__ bin, int n) {
    __shared__ float Ws[K * 64];
    __shared__ float bs[K];
    for (int i = threadIdx.x; i < K * 64; i += blockDim.x) Ws[i] = W[i];
    if (SRC_AGG)
        for (int i = threadIdx.x; i < K; i += blockDim.x) bs[i] = bin[i];
    __syncthreads();

    int node = blockIdx.x * blockDim.x + threadIdx.x;
    if (node >= n) return;

    float acc[64];
#pragma unroll
    for (int j = 0; j < 64; j++) acc[j] = 0.0f;

    const float* row = SRC_AGG ? (g_agg + (size_t)node * K) : (in + (size_t)node * K);
    const float4* row4 = reinterpret_cast<const float4*>(row);
#pragma unroll
    for (int k4 = 0; k4 < K / 4; k4++) {
        float4 v4 = row4[k4];
        float v[4] = {v4.x, v4.y, v4.z, v4.w};
#pragma unroll
        for (int kk = 0; kk < 4; kk++) {
            int k = k4 * 4 + kk;
            float vv = v[kk];
            if (SRC_AGG) vv = fmaxf(vv + bs[k], 0.0f);
#pragma unroll
            for (int j = 0; j < 64; j++) acc[j] = fmaf(vv, Ws[k * 64 + j], acc[j]);
        }
    }
    float4* o = reinterpret_cast<float4*>(g_h + (size_t)node * 64);
#pragma unroll
    for (int j = 0; j < 16; j++)
        o[j] = make_float4(acc[4 * j], acc[4 * j + 1], acc[4 * j + 2], acc[4 * j + 3]);
}

// ---------------- gather: one warp per node, 2 floats per lane -------------
// agg[d] = dinv[d] * ( sum_e w_e*h[src_e] + dinv[d]*h[d] ),  w_e = dinv[src]
__global__ void k_gather(int n) {
    int warp = (blockIdx.x * blockDim.x + threadIdx.x) >> 5;
    if (warp >= n) return;
    int lane = threadIdx.x & 31;

    const int beg = g_off[warp];
    const int cnt = g_degi[warp];
    const float dv = g_dinv[warp];
    const float2* hp = reinterpret_cast<const float2*>(g_h);

    // self loop contribution: dinv[d]*h[d]
    float2 self = hp[(size_t)warp * 32 + lane];
    float ax = self.x * dv, ay = self.y * dv;
    float bx = 0.f, by = 0.f;
    float cx = 0.f, cy = 0.f;
    float dx = 0.f, dy = 0.f;

    int e = 0;
    for (; e + 4 <= cnt; e += 4) {
        Ent e0 = g_csr[beg + e];
        Ent e1 = g_csr[beg + e + 1];
        Ent e2 = g_csr[beg + e + 2];
        Ent e3 = g_csr[beg + e + 3];
        float2 v0 = hp[(size_t)e0.s * 32 + lane];
        float2 v1 = hp[(size_t)e1.s * 32 + lane];
        float2 v2 = hp[(size_t)e2.s * 32 + lane];
        float2 v3 = hp[(size_t)e3.s * 32 + lane];
        ax = fmaf(v0.x, e0.w, ax); ay = fmaf(v0.y, e0.w, ay);
        bx = fmaf(v1.x, e1.w, bx); by = fmaf(v1.y, e1.w, by);
        cx = fmaf(v2.x, e2.w, cx); cy = fmaf(v2.y, e2.w, cy);
        dx = fmaf(v3.x, e3.w, dx); dy = fmaf(v3.y, e3.w, dy);
    }
    for (; e < cnt; e++) {
        Ent e0 = g_csr[beg + e];
        float2 v0 = hp[(size_t)e0.s * 32 + lane];
        ax = fmaf(v0.x, e0.w, ax); ay = fmaf(v0.y, e0.w, ay);
    }

    float2 r;
    r.x = ((ax + bx) + (cx + dx)) * dv;
    r.y = ((ay + by) + (cy + dy)) * dv;
    reinterpret_cast<float2*>(g_agg)[(size_t)warp * 32 + lane] = r;
}

// ---------------- final head: q = relu(agg + b2) @ Wl + bl ----------------
__global__ void k_head(const float* __restrict__ b2, const float* __restrict__ Wl,
                       const float* __restrict__ bl, float* __restrict__ out, int n) {
    __shared__ float Ws[64 * 2];
    __shared__ float bs[64];
    for (int i = threadIdx.x; i < 128; i += blockDim.x) Ws[i] = Wl[i];
    for (int i = threadIdx.x; i < 64; i += blockDim.x) bs[i] = b2[i];
    __syncthreads();

    int node = blockIdx.x * blockDim.x + threadIdx.x;
    if (node >= n) return;
    const float4* row4 = reinterpret_cast<const float4*>(g_agg + (size_t)node * 64);
    float a0 = 0.0f, a1 = 0.0f;
#pragma unroll
    for (int k4 = 0; k4 < 16; k4++) {
        float4 v4 = row4[k4];
        float v[4] = {v4.x, v4.y, v4.z, v4.w};
#pragma unroll
        for (int kk = 0; kk < 4; kk++) {
            int k = k4 * 4 + kk;
            float vv = fmaxf(v[kk] + bs[k], 0.0f);
            a0 = fmaf(vv, Ws[k * 2 + 0], a0);
            a1 = fmaf(vv, Ws[k * 2 + 1], a1);
        }
    }
    out[(size_t)node * 2 + 0] = a0 + bl[0];
    out[(size_t)node * 2 + 1] = a1 + bl[1];
}

// ---------------------------------------------------------------------------
extern "C" void kernel_launch(void* const* d_in, const int* in_sizes, int n_in,
                              void* d_out, int out_size) {
    const float* x   = (const float*)d_in[0];   // [N,32]
    const void*  ei  = d_in[1];                 // [2,E] int32 or int64
    const float* W1  = (const float*)d_in[2];   // [32,64]
    const float* b1  = (const float*)d_in[3];   // [64]
    const float* W2  = (const float*)d_in[4];   // [64,64]
    const float* b2  = (const float*)d_in[5];   // [64]
    const float* Wl  = (const float*)d_in[6];   // [64,2]
    const float* bl  = (const float*)d_in[7];   // [2]
    float* out       = (float*)d_out;           // [N,2]

    const int N = in_sizes[0] / 32;
    const int E = in_sizes[1] / 2;
    const int T = 256;
    const int NB = (N + 255) / 256;  // scan blocks (<= 256 for N <= 65536)

    int nwords = 2 * E < 4096 ? 2 * E : 4096;

    // CSR build (shared by both layers)
    k_init<<<(N + T - 1) / T, T>>>((const unsigned int*)ei, nwords, N);
    k_count<<<(E + T - 1) / T, T>>>(ei, E);
    k_scan_block<<<NB, 256>>>(N);
    k_scan_top<<<1, 256>>>(NB);
    k_finalize<<<(N + T - 1) / T, T>>>(N);
    k_csr_fill<<<(E + T - 1) / T, T>>>(ei, E);

    const int GW = (N * 32 + T - 1) / T;  // gather grid (warp per node)

    // ---- layer 1 ----
    k_gemm64<32, false><<<(N + 127) / 128, 128>>>(x, W1, nullptr, N);
    k_gather<<<GW, T>>>(N);

    // ---- layer 2 (fused relu(agg+b1) into GEMM input) ----
    k_gemm64<64, true><<<(N + 127) / 128, 128>>>(nullptr, W2, b1, N);
    k_gather<<<GW, T>>>(N);

    // ---- head ----
    k_head<<<(N + T - 1) / T, T>>>(b2, Wl, bl, out, N);
}

// round 6
// speedup vs baseline: 2.6887x; 1.0921x over previous
#include <cuda_runtime.h>
#include <cstdint>

// ---------------------------------------------------------------------------
// GCN 2-layer + linear head. CSR gather, layer-1 reassociated:
//   aggx = Anorm @ x                      (32-feat gather)
//   h1   = relu(aggx @ W1 + b1)           (gemm, fused out bias+relu)
//   t2   = h1 @ W2                        (gemm)
//   out  = rowwise: relu(Anorm@t2 + b2) @ Wl + bl   (gather fused with head)
// ---------------------------------------------------------------------------

#define N_NODES 50000
#define MAX_E   1000000
#define NB_MAX  256

struct alignas(8) Ent { int s; float w; };

__device__ int   g_degi[N_NODES];
__device__ int   g_off[N_NODES];
__device__ int   g_cur[N_NODES];
__device__ float g_dinv[N_NODES];
__device__ Ent   g_csr[MAX_E];
__device__ float g_h[(size_t)N_NODES * 64];    // h1
__device__ float g_agg[(size_t)N_NODES * 64];  // aggx (32 used) then t2
__device__ unsigned long long g_state[NB_MAX]; // lookback scan state
__device__ unsigned int g_ticket;
__device__ int   g_is64;

// ---------------- init: zero deg/scan-state + dtype detect -----------------
__global__ void k_init(const unsigned int* __restrict__ w, int nwords, int n, int nb) {
    int i = blockIdx.x * blockDim.x + threadIdx.x;
    if (i < n) g_degi[i] = 0;
    if (i < nb) g_state[i] = 0ull;
    if (i == 0) g_ticket = 0u;
    if (blockIdx.x == 0) {
        __shared__ int any_nz;
        if (threadIdx.x == 0) any_nz = 0;
        __syncthreads();
        for (int j = threadIdx.x * 2 + 1; j < nwords; j += blockDim.x * 2) {
            if (w[j] != 0u) { any_nz = 1; break; }
        }
        __syncthreads();
        if (threadIdx.x == 0) g_is64 = any_nz ? 0 : 1;
    }
}

__device__ __forceinline__ int edge_at(const void* __restrict__ ei, int i) {
    if (g_is64) return (int)((const long long*)ei)[i];
    return ((const int*)ei)[i];
}

__global__ void k_count(const void* __restrict__ ei, int E) {
    int e = blockIdx.x * blockDim.x + threadIdx.x;
    if (e < E) atomicAdd(&g_degi[edge_at(ei, E + e)], 1);
}

// ------------- single-pass scan (decoupled lookback) + finalize -------------
// status in bits[33:32]: 1 = aggregate ready, 2 = inclusive prefix ready.
__global__ void k_scan(int n) {
    __shared__ int s[256];
    __shared__ int sh_bid;
    __shared__ int sh_excl;
    if (threadIdx.x == 0) sh_bid = atomicAdd(&g_ticket, 1u);
    __syncthreads();
    const int bid = sh_bid;
    const int i = bid * 256 + threadIdx.x;
    const int v = (i < n) ? g_degi[i] : 0;
    s[threadIdx.x] = v;
    __syncthreads();
#pragma unroll
    for (int off = 1; off < 256; off <<= 1) {
        int t = (threadIdx.x >= off) ? s[threadIdx.x - off] : 0;
        __syncthreads();
        s[threadIdx.x] += t;
        __syncthreads();
    }
    const int incl = s[threadIdx.x];
    const int agg = s[255];

    if (threadIdx.x == 0) {
        volatile unsigned long long* st = g_state;
        if (bid == 0) {
            st[0] = (2ull << 32) | (unsigned)agg;
            sh_excl = 0;
        } else {
            st[bid] = (1ull << 32) | (unsigned)agg;
            int run = 0;
            int j = bid - 1;
            while (true) {
                unsigned long long w;
                do { w = st[j]; } while ((w >> 32) == 0);
                run += (int)(unsigned)w;
                if ((w >> 32) == 2ull) break;
                j--;
            }
            st[bid] = (2ull << 32) | (unsigned)(run + agg);
            sh_excl = run;
        }
    }
    __syncthreads();

    if (i < n) {
        int off = sh_excl + incl - v;  // exclusive prefix
        g_off[i] = off;
        g_cur[i] = off;
        g_dinv[i] = rsqrtf((float)(v + 1));
    }
}

// ---------------- CSR fill: (src, dinv[src]) ----------------
__global__ void k_csr_fill(const void* __restrict__ ei, int E) {
    int e = blockIdx.x * blockDim.x + threadIdx.x;
    if (e >= E) return;
    int s = edge_at(ei, e);
    int d = edge_at(ei, E + e);
    int slot = atomicAdd(&g_cur[d], 1);
    Ent en; en.s = s; en.w = g_dinv[s];
    g_csr[slot] = en;
}

// ------------- gather over x (32 feats): g_agg[n,32] = Anorm @ x -------------
__global__ void k_gather_x(const float* __restrict__ x, int n) {
    int warp = (blockIdx.x * blockDim.x + threadIdx.x) >> 5;
    if (warp >= n) return;
    int lane = threadIdx.x & 31;

    const int beg = g_off[warp];
    const int cnt = g_degi[warp];
    const float dv = g_dinv[warp];

    float a = x[(size_t)warp * 32 + lane] * dv;  // self loop
    float b = 0.f, c = 0.f, d = 0.f;

    int e = 0;
    for (; e + 4 <= cnt; e += 4) {
        Ent e0 = g_csr[beg + e];
        Ent e1 = g_csr[beg + e + 1];
        Ent e2 = g_csr[beg + e + 2];
        Ent e3 = g_csr[beg + e + 3];
        float v0 = x[(size_t)e0.s * 32 + lane];
        float v1 = x[(size_t)e1.s * 32 + lane];
        float v2 = x[(size_t)e2.s * 32 + lane];
        float v3 = x[(size_t)e3.s * 32 + lane];
        a = fmaf(v0, e0.w, a);
        b = fmaf(v1, e1.w, b);
        c = fmaf(v2, e2.w, c);
        d = fmaf(v3, e3.w, d);
    }
    for (; e < cnt; e++) {
        Ent e0 = g_csr[beg + e];
        a = fmaf(x[(size_t)e0.s * 32 + lane], e0.w, a);
    }
    g_agg[(size_t)warp * 32 + lane] = ((a + b) + (c + d)) * dv;
}

// ---------------- GEMMs ----------------
// L1 = true : in g_agg[n,32], out g_h[n,64] with out relu(.+b1)
// L1 = false: in g_h[n,64],   out g_agg[n,64], no bias
template <int K, bool L1>
__global__ void k_gemm64(const float* __restrict__ W, const float* __restrict__ bias, int n) {
    __shared__ float Ws[K * 64];
    __shared__ float bs[64];
    for (int i = threadIdx.x; i < K * 64; i += blockDim.x) Ws[i] = W[i];
    if (L1)
        for (int i = threadIdx.x; i < 64; i += blockDim.x) bs[i] = bias[i];
    __syncthreads();

    int node = blockIdx.x * blockDim.x + threadIdx.x;
    if (node >= n) return;

    float acc[64];
#pragma unroll
    for (int j = 0; j < 64; j++) acc[j] = 0.0f;

    const float* in = L1 ? g_agg : g_h;
    const float4* row4 = reinterpret_cast<const float4*>(in + (size_t)node * K);
#pragma unroll
    for (int k4 = 0; k4 < K / 4; k4++) {
        float4 v4 = row4[k4];
        float v[4] = {v4.x, v4.y, v4.z, v4.w};
#pragma unroll
        for (int kk = 0; kk < 4; kk++) {
            int k = k4 * 4 + kk;
#pragma unroll
            for (int j = 0; j < 64; j++) acc[j] = fmaf(v[kk], Ws[k * 64 + j], acc[j]);
        }
    }
    float* outp = L1 ? g_h : g_agg;
    float4* o = reinterpret_cast<float4*>(outp + (size_t)node * 64);
#pragma unroll
    for (int j = 0; j < 16; j++) {
        float4 r;
        r.x = acc[4 * j + 0]; r.y = acc[4 * j + 1];
        r.z = acc[4 * j + 2]; r.w = acc[4 * j + 3];
        if (L1) {
            r.x = fmaxf(r.x + bs[4 * j + 0], 0.f);
            r.y = fmaxf(r.y + bs[4 * j + 1], 0.f);
            r.z = fmaxf(r.z + bs[4 * j + 2], 0.f);
            r.w = fmaxf(r.w + bs[4 * j + 3], 0.f);
        }
        o[j] = r;
    }
}

// ------ gather over t2 (64 feats) fused with head: out = relu(agg+b2)@Wl+bl ------
__global__ void k_gather_head(const float* __restrict__ b2, const float* __restrict__ Wl,
                              const float* __restrict__ bl, float* __restrict__ out, int n) {
    __shared__ float bs[64];
    __shared__ float Ws[128];
    __shared__ float bls[2];
    for (int i = threadIdx.x; i < 64; i += blockDim.x) bs[i] = b2[i];
    for (int i = threadIdx.x; i < 128; i += blockDim.x) Ws[i] = Wl[i];
    if (threadIdx.x < 2) bls[threadIdx.x] = bl[threadIdx.x];
    __syncthreads();

    int warp = (blockIdx.x * blockDim.x + threadIdx.x) >> 5;
    if (warp >= n) return;
    int lane = threadIdx.x & 31;

    const int beg = g_off[warp];
    const int cnt = g_degi[warp];
    const float dv = g_dinv[warp];
    const float2* hp = reinterpret_cast<const float2*>(g_agg);

    float2 self = hp[(size_t)warp * 32 + lane];
    float ax = self.x * dv, ay = self.y * dv;
    float bx = 0.f, by = 0.f;
    float cx = 0.f, cy = 0.f;
    float dx = 0.f, dy = 0.f;

    int e = 0;
    for (; e + 4 <= cnt; e += 4) {
        Ent e0 = g_csr[beg + e];
        Ent e1 = g_csr[beg + e + 1];
        Ent e2 = g_csr[beg + e + 2];
        Ent e3 = g_csr[beg + e + 3];
        float2 v0 = hp[(size_t)e0.s * 32 + lane];
        float2 v1 = hp[(size_t)e1.s * 32 + lane];
        float2 v2 = hp[(size_t)e2.s * 32 + lane];
        float2 v3 = hp[(size_t)e3.s * 32 + lane];
        ax = fmaf(v0.x, e0.w, ax); ay = fmaf(v0.y, e0.w, ay);
        bx = fmaf(v1.x, e1.w, bx); by = fmaf(v1.y, e1.w, by);
        cx = fmaf(v2.x, e2.w, cx); cy = fmaf(v2.y, e2.w, cy);
        dx = fmaf(v3.x, e3.w, dx); dy = fmaf(v3.y, e3.w, dy);
    }
    for (; e < cnt; e++) {
        Ent e0 = g_csr[beg + e];
        float2 v0 = hp[(size_t)e0.s * 32 + lane];
        ax = fmaf(v0.x, e0.w, ax); ay = fmaf(v0.y, e0.w, ay);
    }

    // agg features for this lane: k0 = 2*lane, k1 = 2*lane+1
    float f0 = fmaxf(((ax + bx) + (cx + dx)) * dv + bs[2 * lane + 0], 0.f);
    float f1 = fmaxf(((ay + by) + (cy + dy)) * dv + bs[2 * lane + 1], 0.f);

    float a0 = f0 * Ws[(2 * lane) * 2 + 0] + f1 * Ws[(2 * lane + 1) * 2 + 0];
    float a1 = f0 * Ws[(2 * lane) * 2 + 1] + f1 * Ws[(2 * lane + 1) * 2 + 1];
#pragma unroll
    for (int off = 16; off > 0; off >>= 1) {
        a0 += __shfl_xor_sync(0xffffffffu, a0, off);
        a1 += __shfl_xor_sync(0xffffffffu, a1, off);
    }
    if (lane == 0) {
        out[(size_t)warp * 2 + 0] = a0 + bls[0];
        out[(size_t)warp * 2 + 1] = a1 + bls[1];
    }
}

// ---------------------------------------------------------------------------
extern "C" void kernel_launch(void* const* d_in, const int* in_sizes, int n_in,
                              void* d_out, int out_size) {
    const float* x   = (const float*)d_in[0];   // [N,32]
    const void*  ei  = d_in[1];                 // [2,E] int32 or int64
    const float* W1  = (const float*)d_in[2];   // [32,64]
    const float* b1  = (const float*)d_in[3];   // [64]
    const float* W2  = (const float*)d_in[4];   // [64,64]
    const float* b2  = (const float*)d_in[5];   // [64]
    const float* Wl  = (const float*)d_in[6];   // [64,2]
    const float* bl  = (const float*)d_in[7];   // [2]
    float* out       = (float*)d_out;           // [N,2]

    const int N = in_sizes[0] / 32;
    const int E = in_sizes[1] / 2;
    const int T = 256;
    const int NB = (N + 255) / 256;

    int nwords = 2 * E < 4096 ? 2 * E : 4096;

    // CSR build (4 launches)
    k_init<<<(N + T - 1) / T, T>>>((const unsigned int*)ei, nwords, N, NB);
    k_count<<<(E + T - 1) / T, T>>>(ei, E);
    k_scan<<<NB, 256>>>(N);
    k_csr_fill<<<(E + T - 1) / T, T>>>(ei, E);

    const int GW = (N * 32 + T - 1) / T;

    // aggx = Anorm @ x  (32 feats)
    k_gather_x<<<GW, T>>>(x, N);
    // h1 = relu(aggx @ W1 + b1)
    k_gemm64<32, true><<<(N + 127) / 128, 128>>>(W1, b1, N);
    // t2 = h1 @ W2
    k_gemm64<64, false><<<(N + 127) / 128, 128>>>(W2, nullptr, N);
    // out = relu(Anorm@t2 + b2) @ Wl + bl
    k_gather_head<<<GW, T>>>(b2, Wl, bl, out, N);
}